// round 5
// baseline (speedup 1.0000x reference)
#include <cuda_runtime.h>

// BiGNNLayer: out = (features + x) @ W1 + b1 + (x * features) @ W2 + b2
// where x = segment_sum(lap_vals[:,None] * features[lap_cols], lap_rows)
//
// R5: R2 structure (proven 203.6us) with two isolated changes:
//  (a) dense epilogue uses packed fma.rn.f32x2 (FFMA2) -> halves FMA issue count
//  (b) scan_sums fused into add_offsets -> one fewer launch
// hist / scatter / gather are byte-identical to R2.
//
// Inputs (metadata order):
//  0: lap_rows int32[E]  1: lap_cols int32[E]  2: lap_vals f32[E]
//  3: features f32[N,64] 4: W1 f32[64,64] 5: b1 f32[64] 6: W2 f32[64,64] 7: b2 f32[64]
// Output: f32 [N, 64]

constexpr int DIM = 64;
constexpr int MAX_NODES = 100000;
constexpr int MAX_EDGES = 3200000;
constexpr int SCAN_BLOCK = 1024;
constexpr int MAX_SCAN_BLOCKS = 128;   // supports N up to 131072

// Static device scratch (no runtime allocation allowed)
__device__ int    g_counts[MAX_NODES];
__device__ int    g_offsets[MAX_NODES];
__device__ int    g_cursor[MAX_NODES];
__device__ int    g_blocksums[MAX_SCAN_BLOCKS];
__device__ int2   g_sorted[MAX_EDGES];             // (col, val-as-int) row-sorted
__device__ float4 g_x[MAX_NODES * (DIM / 4)];      // x = L @ features

// f32x2 packed helpers
#define FMA_F32X2(acc, a, b) \
    asm("fma.rn.f32x2 %0, %1, %2, %0;" : "+l"(acc) : "l"(a), "l"(b))
#define PACK_F32X2(out, lo, hi) \
    asm("mov.b64 %0, {%1, %2};" : "=l"(out) : "r"(lo), "r"(hi))

__device__ __forceinline__ unsigned long long pack_dup(float v) {
    unsigned long long r;
    unsigned int u = __float_as_uint(v);
    PACK_F32X2(r, u, u);
    return r;
}

__device__ __forceinline__ float2 as_float2(unsigned long long v) {
    float2 f;
    unsigned int lo = (unsigned int)(v & 0xFFFFFFFFull);
    unsigned int hi = (unsigned int)(v >> 32);
    f.x = __uint_as_float(lo);
    f.y = __uint_as_float(hi);
    return f;
}

// ---------------------------------------------------------------------------
// CSR build (identical to R2)
// ---------------------------------------------------------------------------
__global__ void zero_counts_kernel(int n) {
    int i = blockIdx.x * blockDim.x + threadIdx.x;
    if (i < n) g_counts[i] = 0;
}

__global__ void hist_kernel(const int* __restrict__ rows, int n_edges) {
    int e = blockIdx.x * blockDim.x + threadIdx.x;
    if (e < n_edges) atomicAdd(&g_counts[rows[e]], 1);
}

__global__ void scan_block_kernel(int n) {
    __shared__ int s[SCAN_BLOCK];
    int t = threadIdx.x;
    int idx = blockIdx.x * SCAN_BLOCK + t;
    int v = (idx < n) ? g_counts[idx] : 0;
    s[t] = v;
    __syncthreads();
    #pragma unroll
    for (int d = 1; d < SCAN_BLOCK; d <<= 1) {
        int tmp = (t >= d) ? s[t - d] : 0;
        __syncthreads();
        s[t] += tmp;
        __syncthreads();
    }
    if (idx < n) g_offsets[idx] = s[t] - v;                    // exclusive
    if (t == SCAN_BLOCK - 1) g_blocksums[blockIdx.x] = s[t];   // block total
}

// Fused: scan of block sums (replicated per block, cheap) + offset add.
__global__ void add_offsets_kernel(int n, int nblk) {
    __shared__ int s[MAX_SCAN_BLOCKS];
    __shared__ int sx[MAX_SCAN_BLOCKS];
    int t = threadIdx.x;

    int v0 = 0;
    if (t < MAX_SCAN_BLOCKS) {
        v0 = (t < nblk) ? g_blocksums[t] : 0;
        s[t] = v0;
    }
    __syncthreads();
    #pragma unroll
    for (int d = 1; d < MAX_SCAN_BLOCKS; d <<= 1) {
        int tmp = 0;
        if (t < MAX_SCAN_BLOCKS && t >= d) tmp = s[t - d];
        __syncthreads();
        if (t < MAX_SCAN_BLOCKS) s[t] += tmp;
        __syncthreads();
    }
    if (t < MAX_SCAN_BLOCKS) sx[t] = s[t] - v0;   // exclusive
    __syncthreads();

    int i = blockIdx.x * blockDim.x + t;
    if (i < n) {
        int o = g_offsets[i] + sx[i >> 10];
        g_offsets[i] = o;
        g_cursor[i] = o;
    }
}

__global__ void scatter_kernel(const int* __restrict__ rows,
                               const int* __restrict__ cols,
                               const float* __restrict__ vals,
                               int n_edges) {
    int e = blockIdx.x * blockDim.x + threadIdx.x;
    if (e >= n_edges) return;
    int r = rows[e];
    int pos = atomicAdd(&g_cursor[r], 1);
    g_sorted[pos] = make_int2(cols[e], __float_as_int(vals[e]));
}

// ---------------------------------------------------------------------------
// Gather SpMM (identical to R2): one warp per row, lane owns dims {lane, lane+32}.
// ---------------------------------------------------------------------------
__global__ void gather_kernel(const float* __restrict__ feat, int n_nodes) {
    int warp = (blockIdx.x * blockDim.x + threadIdx.x) >> 5;
    int lane = threadIdx.x & 31;
    if (warp >= n_nodes) return;

    int off = g_offsets[warp];
    int deg = g_counts[warp];

    float a0 = 0.f, a1 = 0.f;
    int i = 0;
    for (; i + 4 <= deg; i += 4) {
        int2 p0 = g_sorted[off + i + 0];
        int2 p1 = g_sorted[off + i + 1];
        int2 p2 = g_sorted[off + i + 2];
        int2 p3 = g_sorted[off + i + 3];
        const float* f0 = feat + (size_t)p0.x * DIM;
        const float* f1 = feat + (size_t)p1.x * DIM;
        const float* f2 = feat + (size_t)p2.x * DIM;
        const float* f3 = feat + (size_t)p3.x * DIM;
        float g00 = __ldg(f0 + lane), g01 = __ldg(f0 + lane + 32);
        float g10 = __ldg(f1 + lane), g11 = __ldg(f1 + lane + 32);
        float g20 = __ldg(f2 + lane), g21 = __ldg(f2 + lane + 32);
        float g30 = __ldg(f3 + lane), g31 = __ldg(f3 + lane + 32);
        float v0 = __int_as_float(p0.y), v1 = __int_as_float(p1.y);
        float v2 = __int_as_float(p2.y), v3 = __int_as_float(p3.y);
        a0 += v0 * g00; a1 += v0 * g01;
        a0 += v1 * g10; a1 += v1 * g11;
        a0 += v2 * g20; a1 += v2 * g21;
        a0 += v3 * g30; a1 += v3 * g31;
    }
    for (; i < deg; ++i) {
        int2 p = g_sorted[off + i];
        float v = __int_as_float(p.y);
        const float* f = feat + (size_t)p.x * DIM;
        a0 += v * __ldg(f + lane);
        a1 += v * __ldg(f + lane + 32);
    }

    float* xp = reinterpret_cast<float*>(g_x);
    xp[(size_t)warp * DIM + lane]      = a0;
    xp[(size_t)warp * DIM + lane + 32] = a1;
}

// ---------------------------------------------------------------------------
// Dense epilogue with f32x2 packed FMA.
// Block = 64-node tile, 256 threads. Thread = 2 nodes x 8 cols.
// Accumulators are f32x2 over column pairs; the per-(node,k) broadcast scalar
// is packed once (mov.b64) and reused across 4 col-pairs x 2 matrices.
// Per k per thread: 4 LDS.32 + 4 PACK + 4 LDG.128 + 16 FFMA2  (vs 32 FFMA).
// ---------------------------------------------------------------------------
constexpr int YPAD = 68;  // 64 + 4: float4-aligned staging, breaks conflicts

__global__ __launch_bounds__(256) void dense_kernel(
        const float4* __restrict__ feat,
        const float*  __restrict__ W1,
        const float*  __restrict__ b1,
        const float*  __restrict__ W2,
        const float*  __restrict__ b2,
        float4* __restrict__ out,
        int n_nodes) {
    __shared__ float y1s[64 * YPAD];
    __shared__ float y2s[64 * YPAD];

    int t = threadIdx.x;
    int node0 = blockIdx.x * 64;

    const float4* x4 = reinterpret_cast<const float4*>(g_x);

    // Stage y1 = f + x, y2 = f * x for 64 nodes (coalesced float4 loads).
    #pragma unroll
    for (int q = 0; q < 4; ++q) {
        int idx = q * 256 + t;           // 0..1023
        int nl = idx >> 4;               // local node 0..63
        int k4 = idx & 15;               // float4 chunk 0..15
        int node = node0 + nl;
        float4 f = make_float4(0.f, 0.f, 0.f, 0.f);
        float4 x = make_float4(0.f, 0.f, 0.f, 0.f);
        if (node < n_nodes) {
            f = __ldcs(feat + (size_t)node * 16 + k4);
            x = __ldcs(x4 + (size_t)node * 16 + k4);
        }
        float* p1 = &y1s[nl * YPAD + k4 * 4];
        float* p2 = &y2s[nl * YPAD + k4 * 4];
        p1[0] = f.x + x.x; p1[1] = f.y + x.y; p1[2] = f.z + x.z; p1[3] = f.w + x.w;
        p2[0] = f.x * x.x; p2[1] = f.y * x.y; p2[2] = f.z * x.z; p2[3] = f.w * x.w;
    }
    __syncthreads();

    int cg = t & 7;          // col group: j0 = cg*8
    int ng = t >> 3;         // node pair: n0 = ng*2
    int j0 = cg * 8;
    int n0 = ng * 2;

    unsigned long long acc[2][4];
    #pragma unroll
    for (int i = 0; i < 2; ++i)
        #pragma unroll
        for (int c = 0; c < 4; ++c) acc[i][c] = 0ull;  // (0.0f, 0.0f)

    #pragma unroll 8
    for (int k = 0; k < DIM; ++k) {
        float a10 = y1s[n0 * YPAD + k];
        float a20 = y2s[n0 * YPAD + k];
        float a11 = y1s[(n0 + 1) * YPAD + k];
        float a21 = y2s[(n0 + 1) * YPAD + k];
        unsigned long long A10 = pack_dup(a10);
        unsigned long long A20 = pack_dup(a20);
        unsigned long long A11 = pack_dup(a11);
        unsigned long long A21 = pack_dup(a21);

        const ulonglong2* w1q = reinterpret_cast<const ulonglong2*>(W1 + k * DIM + j0);
        const ulonglong2* w2q = reinterpret_cast<const ulonglong2*>(W2 + k * DIM + j0);
        ulonglong2 wA = __ldg(w1q);      // cols (j0,j0+1), (j0+2,j0+3)
        ulonglong2 wB = __ldg(w1q + 1);  // cols (j0+4,j0+5), (j0+6,j0+7)
        ulonglong2 vA = __ldg(w2q);
        ulonglong2 vB = __ldg(w2q + 1);

        FMA_F32X2(acc[0][0], A10, wA.x);
        FMA_F32X2(acc[0][1], A10, wA.y);
        FMA_F32X2(acc[0][2], A10, wB.x);
        FMA_F32X2(acc[0][3], A10, wB.y);
        FMA_F32X2(acc[0][0], A20, vA.x);
        FMA_F32X2(acc[0][1], A20, vA.y);
        FMA_F32X2(acc[0][2], A20, vB.x);
        FMA_F32X2(acc[0][3], A20, vB.y);
        FMA_F32X2(acc[1][0], A11, wA.x);
        FMA_F32X2(acc[1][1], A11, wA.y);
        FMA_F32X2(acc[1][2], A11, wB.x);
        FMA_F32X2(acc[1][3], A11, wB.y);
        FMA_F32X2(acc[1][0], A21, vA.x);
        FMA_F32X2(acc[1][1], A21, vA.y);
        FMA_F32X2(acc[1][2], A21, vB.x);
        FMA_F32X2(acc[1][3], A21, vB.y);
    }

    // bias
    float bb[8];
    #pragma unroll
    for (int c = 0; c < 8; ++c) bb[c] = __ldg(b1 + j0 + c) + __ldg(b2 + j0 + c);

    #pragma unroll
    for (int i = 0; i < 2; ++i) {
        int node = node0 + n0 + i;
        if (node < n_nodes) {
            float2 c01 = as_float2(acc[i][0]);
            float2 c23 = as_float2(acc[i][1]);
            float2 c45 = as_float2(acc[i][2]);
            float2 c67 = as_float2(acc[i][3]);
            out[(size_t)node * 16 + cg * 2]     = make_float4(c01.x + bb[0], c01.y + bb[1],
                                                              c23.x + bb[2], c23.y + bb[3]);
            out[(size_t)node * 16 + cg * 2 + 1] = make_float4(c45.x + bb[4], c45.y + bb[5],
                                                              c67.x + bb[6], c67.y + bb[7]);
        }
    }
}

// ---------------------------------------------------------------------------
extern "C" void kernel_launch(void* const* d_in, const int* in_sizes, int n_in,
                              void* d_out, int out_size) {
    const int*   rows = (const int*)d_in[0];
    const int*   cols = (const int*)d_in[1];
    const float* vals = (const float*)d_in[2];
    const float* feat = (const float*)d_in[3];
    const float* W1   = (const float*)d_in[4];
    const float* b1   = (const float*)d_in[5];
    const float* W2   = (const float*)d_in[6];
    const float* b2   = (const float*)d_in[7];

    int n_edges = in_sizes[0];
    int n_nodes = in_sizes[3] / DIM;

    // 1) CSR build: histogram -> scan -> scatter
    zero_counts_kernel<<<(n_nodes + 255) / 256, 256>>>(n_nodes);
    hist_kernel<<<(n_edges + 255) / 256, 256>>>(rows, n_edges);

    int nblk = (n_nodes + SCAN_BLOCK - 1) / SCAN_BLOCK;
    scan_block_kernel<<<nblk, SCAN_BLOCK>>>(n_nodes);
    add_offsets_kernel<<<(n_nodes + 255) / 256, 256>>>(n_nodes, nblk);

    scatter_kernel<<<(n_edges + 255) / 256, 256>>>(rows, cols, vals, n_edges);

    // 2) atomic-free gather SpMM: one warp per row
    long long threads = (long long)n_nodes * 32;
    gather_kernel<<<(int)((threads + 255) / 256), 256>>>(feat, n_nodes);

    // 3) dense epilogue (f32x2)
    dense_kernel<<<(n_nodes + 63) / 64, 256>>>((const float4*)feat, W1, b1,
                                               W2, b2, (float4*)d_out, n_nodes);
}

// round 6
// speedup vs baseline: 1.0922x; 1.0922x over previous
#include <cuda_runtime.h>
#include <cuda_bf16.h>

// BiGNNLayer: out = (features + x) @ W1 + b1 + (x * features) @ W2 + b2
// where x = segment_sum(lap_vals[:,None] * features[lap_cols], lap_rows)
//
// R6 = R2 (proven 203.6us) + fused block-sum scan (validated in R5)
//      + ONE change: bf16 feature table for the gather phase.
//   Gather is LTS-bandwidth-bound (~845MB @ ~8.5TB/s); bf16 halves the
//   dominant per-edge feature traffic (256B -> 128B). Dense epilogue still
//   uses full fp32 features; only x picks up ~1e-3 relative bf16 noise,
//   which attenuates to ~3-5e-4 at the output (threshold 1e-3).
//
// Inputs (metadata order):
//  0: lap_rows int32[E]  1: lap_cols int32[E]  2: lap_vals f32[E]
//  3: features f32[N,64] 4: W1 f32[64,64] 5: b1 f32[64] 6: W2 f32[64,64] 7: b2 f32[64]
// Output: f32 [N, 64]

constexpr int DIM = 64;
constexpr int MAX_NODES = 100000;
constexpr int MAX_EDGES = 3200000;
constexpr int SCAN_BLOCK = 1024;
constexpr int MAX_SCAN_BLOCKS = 128;   // supports N up to 131072

// Static device scratch (no runtime allocation allowed)
__device__ int    g_counts[MAX_NODES];
__device__ int    g_offsets[MAX_NODES];
__device__ int    g_cursor[MAX_NODES];
__device__ int    g_blocksums[MAX_SCAN_BLOCKS];
__device__ int2   g_sorted[MAX_EDGES];                 // (col, val-as-int) row-sorted
__device__ float4 g_x[MAX_NODES * (DIM / 4)];          // x = L @ features (fp32)
__device__ __nv_bfloat162 g_fb[MAX_NODES * (DIM / 2)]; // bf16 feature table

// ---------------------------------------------------------------------------
// CSR build (R2 forms)
// ---------------------------------------------------------------------------
__global__ void zero_counts_kernel(int n) {
    int i = blockIdx.x * blockDim.x + threadIdx.x;
    if (i < n) g_counts[i] = 0;
}

__global__ void hist_kernel(const int* __restrict__ rows, int n_edges) {
    int e = blockIdx.x * blockDim.x + threadIdx.x;
    if (e < n_edges) atomicAdd(&g_counts[rows[e]], 1);
}

// Feature table fp32 -> bf16 (runs right after hist; independent of counts).
__global__ void convert_kernel(const float2* __restrict__ feat, int n2) {
    int i = blockIdx.x * blockDim.x + threadIdx.x;
    if (i < n2) {
        float2 f = __ldg(feat + i);
        g_fb[i] = __float22bfloat162_rn(f);
    }
}

__global__ void scan_block_kernel(int n) {
    __shared__ int s[SCAN_BLOCK];
    int t = threadIdx.x;
    int idx = blockIdx.x * SCAN_BLOCK + t;
    int v = (idx < n) ? g_counts[idx] : 0;
    s[t] = v;
    __syncthreads();
    #pragma unroll
    for (int d = 1; d < SCAN_BLOCK; d <<= 1) {
        int tmp = (t >= d) ? s[t - d] : 0;
        __syncthreads();
        s[t] += tmp;
        __syncthreads();
    }
    if (idx < n) g_offsets[idx] = s[t] - v;                    // exclusive
    if (t == SCAN_BLOCK - 1) g_blocksums[blockIdx.x] = s[t];   // block total
}

// Fused: per-block re-scan of block sums (<=128) + offset add. (validated R5)
__global__ void add_offsets_kernel(int n, int nblk) {
    __shared__ int s[MAX_SCAN_BLOCKS];
    __shared__ int sx[MAX_SCAN_BLOCKS];
    int t = threadIdx.x;

    int v0 = 0;
    if (t < MAX_SCAN_BLOCKS) {
        v0 = (t < nblk) ? g_blocksums[t] : 0;
        s[t] = v0;
    }
    __syncthreads();
    #pragma unroll
    for (int d = 1; d < MAX_SCAN_BLOCKS; d <<= 1) {
        int tmp = 0;
        if (t < MAX_SCAN_BLOCKS && t >= d) tmp = s[t - d];
        __syncthreads();
        if (t < MAX_SCAN_BLOCKS) s[t] += tmp;
        __syncthreads();
    }
    if (t < MAX_SCAN_BLOCKS) sx[t] = s[t] - v0;   // exclusive
    __syncthreads();

    int i = blockIdx.x * blockDim.x + t;
    if (i < n) {
        int o = g_offsets[i] + sx[i >> 10];
        g_offsets[i] = o;
        g_cursor[i] = o;
    }
}

__global__ void scatter_kernel(const int* __restrict__ rows,
                               const int* __restrict__ cols,
                               const float* __restrict__ vals,
                               int n_edges) {
    int e = blockIdx.x * blockDim.x + threadIdx.x;
    if (e >= n_edges) return;
    int r = rows[e];
    int pos = atomicAdd(&g_cursor[r], 1);
    g_sorted[pos] = make_int2(cols[e], __float_as_int(vals[e]));
}

// ---------------------------------------------------------------------------
// Gather SpMM over the bf16 table: one warp per row.
// Lane owns dims {2*lane, 2*lane+1}: ONE LDG.32 (bf16x2) per edge per lane
// = 128B/warp/edge, fully coalesced. 8-edge unroll for MLP.
// Accumulation in fp32.
// ---------------------------------------------------------------------------
__global__ __launch_bounds__(256) void gather_kernel(int n_nodes) {
    int warp = (blockIdx.x * blockDim.x + threadIdx.x) >> 5;
    int lane = threadIdx.x & 31;
    if (warp >= n_nodes) return;

    int off = g_offsets[warp];
    int deg = g_counts[warp];

    float ax = 0.f, ay = 0.f;
    int i = 0;
    for (; i + 8 <= deg; i += 8) {
        int2 p[8];
        #pragma unroll
        for (int u = 0; u < 8; ++u) p[u] = __ldg(&g_sorted[off + i + u]);
        __nv_bfloat162 g[8];
        #pragma unroll
        for (int u = 0; u < 8; ++u)
            g[u] = __ldg(&g_fb[(size_t)p[u].x * 32 + lane]);
        #pragma unroll
        for (int u = 0; u < 8; ++u) {
            float v = __int_as_float(p[u].y);
            float2 gf = __bfloat1622float2(g[u]);
            ax += v * gf.x;
            ay += v * gf.y;
        }
    }
    for (; i < deg; ++i) {
        int2 p = __ldg(&g_sorted[off + i]);
        float v = __int_as_float(p.y);
        float2 gf = __bfloat1622float2(__ldg(&g_fb[(size_t)p.x * 32 + lane]));
        ax += v * gf.x;
        ay += v * gf.y;
    }

    // g_x is row-major fp32 [N, 64]; lane pair (2*lane, 2*lane+1) -> float2 slot
    float2* xp = reinterpret_cast<float2*>(g_x);
    xp[(size_t)warp * 32 + lane] = make_float2(ax, ay);
}

// ---------------------------------------------------------------------------
// Dense epilogue (exact R2 form): block = 64-node tile x 64 cols, 256 threads.
// Thread computes 4 nodes x 4 cols. Full fp32 features.
// ---------------------------------------------------------------------------
constexpr int YPAD = 68;  // 64 + 4, float4-aligned staging, breaks conflicts

__global__ __launch_bounds__(256) void dense_kernel(
        const float4* __restrict__ feat,
        const float*  __restrict__ W1,
        const float*  __restrict__ b1,
        const float*  __restrict__ W2,
        const float*  __restrict__ b2,
        float4* __restrict__ out,
        int n_nodes) {
    __shared__ float y1s[64 * YPAD];
    __shared__ float y2s[64 * YPAD];

    int t = threadIdx.x;
    int node0 = blockIdx.x * 64;

    // Stage y1 = f + x, y2 = f * x for 64 nodes (coalesced float4 loads).
    #pragma unroll
    for (int q = 0; q < 4; ++q) {
        int idx = q * 256 + t;           // 0..1023
        int nl = idx >> 4;               // local node 0..63
        int k4 = idx & 15;               // float4 chunk 0..15
        int node = node0 + nl;
        float4 f = make_float4(0.f, 0.f, 0.f, 0.f);
        float4 x = make_float4(0.f, 0.f, 0.f, 0.f);
        if (node < n_nodes) {
            f = __ldcs(feat + (size_t)node * 16 + k4);
            x = __ldcs(g_x + (size_t)node * 16 + k4);
        }
        float* p1 = &y1s[nl * YPAD + k4 * 4];
        float* p2 = &y2s[nl * YPAD + k4 * 4];
        p1[0] = f.x + x.x; p1[1] = f.y + x.y; p1[2] = f.z + x.z; p1[3] = f.w + x.w;
        p2[0] = f.x * x.x; p2[1] = f.y * x.y; p2[2] = f.z * x.z; p2[3] = f.w * x.w;
    }
    __syncthreads();

    int cg = t & 15;         // col group: j0 = cg*4
    int ng = t >> 4;         // node group: n0 = ng*4
    int j0 = cg * 4;
    int n0 = ng * 4;

    float acc[4][4];
    #pragma unroll
    for (int i = 0; i < 4; ++i)
        #pragma unroll
        for (int c = 0; c < 4; ++c) acc[i][c] = 0.f;

    #pragma unroll 8
    for (int k = 0; k < DIM; ++k) {
        float4 w1 = __ldg(reinterpret_cast<const float4*>(W1 + k * DIM + j0));
        float4 w2 = __ldg(reinterpret_cast<const float4*>(W2 + k * DIM + j0));
        #pragma unroll
        for (int i = 0; i < 4; ++i) {
            float a1 = y1s[(n0 + i) * YPAD + k];   // broadcast across 16 lanes
            float a2 = y2s[(n0 + i) * YPAD + k];
            acc[i][0] += a1 * w1.x + a2 * w2.x;
            acc[i][1] += a1 * w1.y + a2 * w2.y;
            acc[i][2] += a1 * w1.z + a2 * w2.z;
            acc[i][3] += a1 * w1.w + a2 * w2.w;
        }
    }

    float4 bb;
    bb.x = __ldg(b1 + j0 + 0) + __ldg(b2 + j0 + 0);
    bb.y = __ldg(b1 + j0 + 1) + __ldg(b2 + j0 + 1);
    bb.z = __ldg(b1 + j0 + 2) + __ldg(b2 + j0 + 2);
    bb.w = __ldg(b1 + j0 + 3) + __ldg(b2 + j0 + 3);

    #pragma unroll
    for (int i = 0; i < 4; ++i) {
        int node = node0 + n0 + i;
        if (node < n_nodes) {
            out[(size_t)node * 16 + cg] = make_float4(acc[i][0] + bb.x,
                                                      acc[i][1] + bb.y,
                                                      acc[i][2] + bb.z,
                                                      acc[i][3] + bb.w);
        }
    }
}

// ---------------------------------------------------------------------------
extern "C" void kernel_launch(void* const* d_in, const int* in_sizes, int n_in,
                              void* d_out, int out_size) {
    const int*   rows = (const int*)d_in[0];
    const int*   cols = (const int*)d_in[1];
    const float* vals = (const float*)d_in[2];
    const float* feat = (const float*)d_in[3];
    const float* W1   = (const float*)d_in[4];
    const float* b1   = (const float*)d_in[5];
    const float* W2   = (const float*)d_in[6];
    const float* b2   = (const float*)d_in[7];

    int n_edges = in_sizes[0];
    int n_nodes = in_sizes[3] / DIM;

    // 1) CSR build: histogram -> (convert) -> scan -> scatter
    zero_counts_kernel<<<(n_nodes + 255) / 256, 256>>>(n_nodes);
    hist_kernel<<<(n_edges + 255) / 256, 256>>>(rows, n_edges);

    int n2 = n_nodes * (DIM / 2);
    convert_kernel<<<(n2 + 255) / 256, 256>>>((const float2*)feat, n2);

    int nblk = (n_nodes + SCAN_BLOCK - 1) / SCAN_BLOCK;
    scan_block_kernel<<<nblk, SCAN_BLOCK>>>(n_nodes);
    add_offsets_kernel<<<(n_nodes + 255) / 256, 256>>>(n_nodes, nblk);

    scatter_kernel<<<(n_edges + 255) / 256, 256>>>(rows, cols, vals, n_edges);

    // 2) atomic-free gather SpMM over bf16 table: one warp per row
    long long threads = (long long)n_nodes * 32;
    gather_kernel<<<(int)((threads + 255) / 256), 256>>>(n_nodes);

    // 3) dense epilogue (exact R2 form, fp32)
    dense_kernel<<<(n_nodes + 63) / 64, 256>>>((const float4*)feat, W1, b1,
                                               W2, b2, (float4*)d_out, n_nodes);
}

// round 7
// speedup vs baseline: 1.1947x; 1.0939x over previous
#include <cuda_runtime.h>

// BiGNNLayer: out = (features + x) @ W1 + b1 + (x * features) @ W2 + b2
// where x = segment_sum(lap_vals[:,None] * features[lap_cols], lap_rows)
//
// R7 = R2 (proven 203.6us, full fp32) + fused scan (validated)
//      + gather 8-edge unroll (R2's exact scalar lane/lane+32 layout, 2x MLP)
//      + dense k-blocked float4 smem loads (same mapping, fewer issues)
//
// Inputs (metadata order):
//  0: lap_rows int32[E]  1: lap_cols int32[E]  2: lap_vals f32[E]
//  3: features f32[N,64] 4: W1 f32[64,64] 5: b1 f32[64] 6: W2 f32[64,64] 7: b2 f32[64]
// Output: f32 [N, 64]

constexpr int DIM = 64;
constexpr int MAX_NODES = 100000;
constexpr int MAX_EDGES = 3200000;
constexpr int SCAN_BLOCK = 1024;
constexpr int MAX_SCAN_BLOCKS = 128;   // supports N up to 131072

// Static device scratch (no runtime allocation allowed)
__device__ int    g_counts[MAX_NODES];
__device__ int    g_offsets[MAX_NODES];
__device__ int    g_cursor[MAX_NODES];
__device__ int    g_blocksums[MAX_SCAN_BLOCKS];
__device__ int2   g_sorted[MAX_EDGES];             // (col, val-as-int) row-sorted
__device__ float4 g_x[MAX_NODES * (DIM / 4)];      // x = L @ features

// ---------------------------------------------------------------------------
// CSR build
// ---------------------------------------------------------------------------
__global__ void zero_counts_kernel(int n) {
    int i = blockIdx.x * blockDim.x + threadIdx.x;
    if (i < n) g_counts[i] = 0;
}

__global__ void hist_kernel(const int* __restrict__ rows, int n_edges) {
    int e = blockIdx.x * blockDim.x + threadIdx.x;
    if (e < n_edges) atomicAdd(&g_counts[rows[e]], 1);
}

__global__ void scan_block_kernel(int n) {
    __shared__ int s[SCAN_BLOCK];
    int t = threadIdx.x;
    int idx = blockIdx.x * SCAN_BLOCK + t;
    int v = (idx < n) ? g_counts[idx] : 0;
    s[t] = v;
    __syncthreads();
    #pragma unroll
    for (int d = 1; d < SCAN_BLOCK; d <<= 1) {
        int tmp = (t >= d) ? s[t - d] : 0;
        __syncthreads();
        s[t] += tmp;
        __syncthreads();
    }
    if (idx < n) g_offsets[idx] = s[t] - v;                    // exclusive
    if (t == SCAN_BLOCK - 1) g_blocksums[blockIdx.x] = s[t];   // block total
}

// Fused: per-block re-scan of block sums (<=128) + offset add. (validated R5)
__global__ void add_offsets_kernel(int n, int nblk) {
    __shared__ int s[MAX_SCAN_BLOCKS];
    __shared__ int sx[MAX_SCAN_BLOCKS];
    int t = threadIdx.x;

    int v0 = 0;
    if (t < MAX_SCAN_BLOCKS) {
        v0 = (t < nblk) ? g_blocksums[t] : 0;
        s[t] = v0;
    }
    __syncthreads();
    #pragma unroll
    for (int d = 1; d < MAX_SCAN_BLOCKS; d <<= 1) {
        int tmp = 0;
        if (t < MAX_SCAN_BLOCKS && t >= d) tmp = s[t - d];
        __syncthreads();
        if (t < MAX_SCAN_BLOCKS) s[t] += tmp;
        __syncthreads();
    }
    if (t < MAX_SCAN_BLOCKS) sx[t] = s[t] - v0;   // exclusive
    __syncthreads();

    int i = blockIdx.x * blockDim.x + t;
    if (i < n) {
        int o = g_offsets[i] + sx[i >> 10];
        g_offsets[i] = o;
        g_cursor[i] = o;
    }
}

__global__ void scatter_kernel(const int* __restrict__ rows,
                               const int* __restrict__ cols,
                               const float* __restrict__ vals,
                               int n_edges) {
    int e = blockIdx.x * blockDim.x + threadIdx.x;
    if (e >= n_edges) return;
    int r = rows[e];
    int pos = atomicAdd(&g_cursor[r], 1);
    g_sorted[pos] = make_int2(cols[e], __float_as_int(vals[e]));
}

// ---------------------------------------------------------------------------
// Gather SpMM: one warp per row, lane owns dims {lane, lane+32} (R2 layout).
// 8-edge unroll -> 16 independent feature loads in flight per lane.
// ---------------------------------------------------------------------------
__global__ __launch_bounds__(256) void gather_kernel(const float* __restrict__ feat,
                                                     int n_nodes) {
    int warp = (blockIdx.x * blockDim.x + threadIdx.x) >> 5;
    int lane = threadIdx.x & 31;
    if (warp >= n_nodes) return;

    int off = g_offsets[warp];
    int deg = g_counts[warp];

    float a0 = 0.f, a1 = 0.f;
    int i = 0;
    for (; i + 8 <= deg; i += 8) {
        int2 p[8];
        #pragma unroll
        for (int u = 0; u < 8; ++u) p[u] = __ldg(&g_sorted[off + i + u]);
        float g0[8], g1[8];
        #pragma unroll
        for (int u = 0; u < 8; ++u) {
            const float* f = feat + (size_t)p[u].x * DIM;
            g0[u] = __ldg(f + lane);
            g1[u] = __ldg(f + lane + 32);
        }
        #pragma unroll
        for (int u = 0; u < 8; ++u) {
            float v = __int_as_float(p[u].y);
            a0 += v * g0[u];
            a1 += v * g1[u];
        }
    }
    for (; i < deg; ++i) {
        int2 p = __ldg(&g_sorted[off + i]);
        float v = __int_as_float(p.y);
        const float* f = feat + (size_t)p.x * DIM;
        a0 += v * __ldg(f + lane);
        a1 += v * __ldg(f + lane + 32);
    }

    float* xp = reinterpret_cast<float*>(g_x);
    xp[(size_t)warp * DIM + lane]      = a0;
    xp[(size_t)warp * DIM + lane + 32] = a1;
}

// ---------------------------------------------------------------------------
// Dense epilogue: block = 64-node tile x 64 cols, 256 threads.
// Thread = 4 nodes x 4 cols (R2 mapping). Inner loop k-blocked by 4 with
// float4 smem loads: per 4k = 8 LDS.128 + 8 LDG.128 + 128 FFMA (was 168 issues).
// ---------------------------------------------------------------------------
constexpr int YPAD = 68;  // 64 + 4, float4-aligned staging, breaks conflicts

__global__ __launch_bounds__(256) void dense_kernel(
        const float4* __restrict__ feat,
        const float*  __restrict__ W1,
        const float*  __restrict__ b1,
        const float*  __restrict__ W2,
        const float*  __restrict__ b2,
        float4* __restrict__ out,
        int n_nodes) {
    __shared__ float y1s[64 * YPAD];
    __shared__ float y2s[64 * YPAD];

    int t = threadIdx.x;
    int node0 = blockIdx.x * 64;

    // Stage y1 = f + x, y2 = f * x for 64 nodes (coalesced float4 loads).
    #pragma unroll
    for (int q = 0; q < 4; ++q) {
        int idx = q * 256 + t;           // 0..1023
        int nl = idx >> 4;               // local node 0..63
        int k4 = idx & 15;               // float4 chunk 0..15
        int node = node0 + nl;
        float4 f = make_float4(0.f, 0.f, 0.f, 0.f);
        float4 x = make_float4(0.f, 0.f, 0.f, 0.f);
        if (node < n_nodes) {
            f = __ldcs(feat + (size_t)node * 16 + k4);
            x = __ldcs(g_x + (size_t)node * 16 + k4);
        }
        float* p1 = &y1s[nl * YPAD + k4 * 4];
        float* p2 = &y2s[nl * YPAD + k4 * 4];
        p1[0] = f.x + x.x; p1[1] = f.y + x.y; p1[2] = f.z + x.z; p1[3] = f.w + x.w;
        p2[0] = f.x * x.x; p2[1] = f.y * x.y; p2[2] = f.z * x.z; p2[3] = f.w * x.w;
    }
    __syncthreads();

    int cg = t & 15;         // col group: j0 = cg*4
    int ng = t >> 4;         // node group: n0 = ng*4
    int j0 = cg * 4;
    int n0 = ng * 4;

    float acc[4][4];
    #pragma unroll
    for (int i = 0; i < 4; ++i)
        #pragma unroll
        for (int c = 0; c < 4; ++c) acc[i][c] = 0.f;

    #pragma unroll
    for (int k = 0; k < DIM; k += 4) {
        // 4 k's of y per node via one LDS.128 each (YPAD=68 keeps 16B alignment)
        float4 a1v[4], a2v[4];
        #pragma unroll
        for (int i = 0; i < 4; ++i) {
            a1v[i] = *reinterpret_cast<const float4*>(&y1s[(n0 + i) * YPAD + k]);
            a2v[i] = *reinterpret_cast<const float4*>(&y2s[(n0 + i) * YPAD + k]);
        }
        #pragma unroll
        for (int kk = 0; kk < 4; ++kk) {
            float4 w1 = __ldg(reinterpret_cast<const float4*>(W1 + (k + kk) * DIM + j0));
            float4 w2 = __ldg(reinterpret_cast<const float4*>(W2 + (k + kk) * DIM + j0));
            #pragma unroll
            for (int i = 0; i < 4; ++i) {
                float a1 = (kk == 0) ? a1v[i].x : (kk == 1) ? a1v[i].y
                         : (kk == 2) ? a1v[i].z : a1v[i].w;
                float a2 = (kk == 0) ? a2v[i].x : (kk == 1) ? a2v[i].y
                         : (kk == 2) ? a2v[i].z : a2v[i].w;
                acc[i][0] += a1 * w1.x + a2 * w2.x;
                acc[i][1] += a1 * w1.y + a2 * w2.y;
                acc[i][2] += a1 * w1.z + a2 * w2.z;
                acc[i][3] += a1 * w1.w + a2 * w2.w;
            }
        }
    }

    float4 bb;
    bb.x = __ldg(b1 + j0 + 0) + __ldg(b2 + j0 + 0);
    bb.y = __ldg(b1 + j0 + 1) + __ldg(b2 + j0 + 1);
    bb.z = __ldg(b1 + j0 + 2) + __ldg(b2 + j0 + 2);
    bb.w = __ldg(b1 + j0 + 3) + __ldg(b2 + j0 + 3);

    #pragma unroll
    for (int i = 0; i < 4; ++i) {
        int node = node0 + n0 + i;
        if (node < n_nodes) {
            out[(size_t)node * 16 + cg] = make_float4(acc[i][0] + bb.x,
                                                      acc[i][1] + bb.y,
                                                      acc[i][2] + bb.z,
                                                      acc[i][3] + bb.w);
        }
    }
}

// ---------------------------------------------------------------------------
extern "C" void kernel_launch(void* const* d_in, const int* in_sizes, int n_in,
                              void* d_out, int out_size) {
    const int*   rows = (const int*)d_in[0];
    const int*   cols = (const int*)d_in[1];
    const float* vals = (const float*)d_in[2];
    const float* feat = (const float*)d_in[3];
    const float* W1   = (const float*)d_in[4];
    const float* b1   = (const float*)d_in[5];
    const float* W2   = (const float*)d_in[6];
    const float* b2   = (const float*)d_in[7];

    int n_edges = in_sizes[0];
    int n_nodes = in_sizes[3] / DIM;

    // 1) CSR build: histogram -> scan -> scatter
    zero_counts_kernel<<<(n_nodes + 255) / 256, 256>>>(n_nodes);
    hist_kernel<<<(n_edges + 255) / 256, 256>>>(rows, n_edges);

    int nblk = (n_nodes + SCAN_BLOCK - 1) / SCAN_BLOCK;
    scan_block_kernel<<<nblk, SCAN_BLOCK>>>(n_nodes);
    add_offsets_kernel<<<(n_nodes + 255) / 256, 256>>>(n_nodes, nblk);

    scatter_kernel<<<(n_edges + 255) / 256, 256>>>(rows, cols, vals, n_edges);

    // 2) atomic-free gather SpMM: one warp per row
    long long threads = (long long)n_nodes * 32;
    gather_kernel<<<(int)((threads + 255) / 256), 256>>>(feat, n_nodes);

    // 3) dense epilogue
    dense_kernel<<<(n_nodes + 63) / 64, 256>>>((const float4*)feat, W1, b1,
                                               W2, b2, (float4*)d_out, n_nodes);
}